// round 8
// baseline (speedup 1.0000x reference)
#include <cuda_runtime.h>
#include <math.h>

#define NN   512
#define DD   128
#define M_TOTAL 2048   // 4*512

// Scratch (device globals: no allocation allowed in kernel_launch)
__device__ float g_Pb[M_TOTAL * DD];  // x@W1 - x@W2 + bias
__device__ float g_Q [M_TOTAL * DD];  // x@W2

// ---------------- packed f32x2 helpers (Blackwell; NO packed max) ----------
typedef unsigned long long ull;

static __device__ __forceinline__ ull pk2(float a) {      // {a, a}
    ull r; unsigned ai = __float_as_uint(a);
    asm("mov.b64 %0, {%1, %1};" : "=l"(r) : "r"(ai));
    return r;
}
static __device__ __forceinline__ ull add2(ull a, ull b) {
    ull r; asm("add.rn.f32x2 %0, %1, %2;" : "=l"(r) : "l"(a), "l"(b));
    return r;
}
static __device__ __forceinline__ ull fma2(ull a, ull b, ull c) {
    ull r; asm("fma.rn.f32x2 %0, %1, %2, %3;" : "=l"(r) : "l"(a), "l"(b), "l"(c));
    return r;
}

union F4U2 { float4 f4; ull u[2]; };

static __device__ __forceinline__ float4 f4max(float4 a, float4 b) {
    float4 r;
    r.x = fmaxf(a.x, b.x); r.y = fmaxf(a.y, b.y);
    r.z = fmaxf(a.z, b.z); r.w = fmaxf(a.w, b.w);
    return r;
}

// ---------------- cp.async helpers ----------------
static __device__ __forceinline__ void cpasync16(unsigned dst, const void* src) {
    asm volatile("cp.async.cg.shared.global [%0], [%1], 16;"
                 :: "r"(dst), "l"(src));
}
#define CP_COMMIT() asm volatile("cp.async.commit_group;")
#define CP_WAIT(n)  asm volatile("cp.async.wait_group %0;" :: "n"(n))

// ---------------------------------------------------------------------------
// Kernel 1: fused dual GEMM, f32x2 FMAs, MLP=16 batched W loads.
//   A1 = x@W1 ; Q = x@W2 ; Pb = A1 - Q + bias (epilogue)
// grid 512 x 128 threads. Block = 4 rows; warp = 1 row; lane = 4 cols.
// No launch_bounds cap: ~90+ regs OK, W loads deeply batched to hide L2.
// ---------------------------------------------------------------------------
__global__
void ec_gemm_kernel(const float* __restrict__ x,
                    const float* __restrict__ W,
                    const float* __restrict__ bias) {
    __shared__ float xs[4][DD];

    const int tid  = threadIdx.x;
    const int w    = tid >> 5;
    const int lane = tid & 31;
    const int rowBase = blockIdx.x * 4;

    ((float4*)xs)[tid] = __ldg(((const float4*)(x + (size_t)rowBase * DD)) + tid);
    __syncthreads();

    ull a1[2] = {0ull, 0ull};
    ull qq[2] = {0ull, 0ull};

    const float4* __restrict__ W4 = (const float4*)W;

    for (int kc = 0; kc < DD; kc += 8) {
        F4U2 wv[16];                           // 8x W1 rows, 8x W2 rows
#pragma unroll
        for (int u = 0; u < 8; ++u) {
            wv[u].f4     = __ldg(&W4[(kc + u) * 32 + lane]);
            wv[8 + u].f4 = __ldg(&W4[(kc + u + DD) * 32 + lane]);
        }
        const float4 xv0 = *(const float4*)&xs[w][kc];
        const float4 xv1 = *(const float4*)&xs[w][kc + 4];
        float xr[8] = {xv0.x, xv0.y, xv0.z, xv0.w, xv1.x, xv1.y, xv1.z, xv1.w};
#pragma unroll
        for (int u = 0; u < 8; ++u) {
            const ull xp = pk2(xr[u]);
            a1[0] = fma2(xp, wv[u].u[0], a1[0]);
            a1[1] = fma2(xp, wv[u].u[1], a1[1]);
            qq[0] = fma2(xp, wv[8 + u].u[0], qq[0]);
            qq[1] = fma2(xp, wv[8 + u].u[1], qq[1]);
        }
    }

    F4U2 A, Q;
    A.u[0] = a1[0]; A.u[1] = a1[1];
    Q.u[0] = qq[0]; Q.u[1] = qq[1];

    const float4 b4 = __ldg(&((const float4*)bias)[lane]);
    float4 P;
    P.x = (A.f4.x - Q.f4.x) + b4.x;
    P.y = (A.f4.y - Q.f4.y) + b4.y;
    P.z = (A.f4.z - Q.f4.z) + b4.z;
    P.w = (A.f4.w - Q.f4.w) + b4.w;

    const int m = rowBase + w;
    ((float4*)g_Pb)[(size_t)m * 32 + lane] = P;
    ((float4*)g_Q )[(size_t)m * 32 + lane] = Q.f4;
}

// ---------------------------------------------------------------------------
// Kernel 2: dense masked max; cp.async double-buffered Q chunks; block-wide
// pre-packed masks (no spills: <= ~50 live regs in the hot loop).
//   out[b,i,o] = max(0, Pb[b,i,o] + max_j (Q[b,j,o] + m[i,j]))
// grid 256 x 512 threads; block = 8 i-rows. Dynamic smem 96 KB:
//   qbuf[2][64*32] float4 (64 KB) | mpack[512][8] ull (32 KB)
// 8 chunks of 64 j; warp w handles j = w*4..w*4+3 of each chunk, all 8 rows.
// ---------------------------------------------------------------------------
__global__ __launch_bounds__(512, 2)
void ec_maxred_kernel(const float* __restrict__ adj,
                      float* __restrict__ out) {
    extern __shared__ char dsm[];
    float4* qbuf = (float4*)dsm;                          // [2][2048]
    ull (*mpack)[8] = (ull (*)[8])(dsm + 65536);          // [512][8]

    const int tid  = threadIdx.x;
    const int w    = tid >> 5;
    const int lane = tid & 31;
    const int i0   = blockIdx.x * 8;     // first global row (b*NN + i)
    const int b    = i0 >> 9;

    const float4* __restrict__ Qb4 = ((const float4*)g_Q) + (size_t)b * NN * 32;

    // ---- stage chunk 0 (async) ----
    {
        unsigned dst0 = (unsigned)__cvta_generic_to_shared(qbuf);
#pragma unroll
        for (int t = 0; t < 4; ++t) {
            const int idx = tid + t * 512;
            cpasync16(dst0 + idx * 16, Qb4 + idx);
        }
        CP_COMMIT();
    }

    // ---- pre-pack ALL masks for this block (overlaps chunk-0 flight) ----
    {
        const int pr = tid >> 6;          // row 0..7
        const int pj = (tid & 63) * 8;    // j base, 8 per thread
        const float4* arow4 =
            (const float4*)(adj + (size_t)(i0 + pr) * NN + pj);
        const float4 a0 = __ldg(arow4);
        const float4 a1 = __ldg(arow4 + 1);
        mpack[pj + 0][pr] = pk2(fmaf(a0.x, 1e38f, -1e38f));
        mpack[pj + 1][pr] = pk2(fmaf(a0.y, 1e38f, -1e38f));
        mpack[pj + 2][pr] = pk2(fmaf(a0.z, 1e38f, -1e38f));
        mpack[pj + 3][pr] = pk2(fmaf(a0.w, 1e38f, -1e38f));
        mpack[pj + 4][pr] = pk2(fmaf(a1.x, 1e38f, -1e38f));
        mpack[pj + 5][pr] = pk2(fmaf(a1.y, 1e38f, -1e38f));
        mpack[pj + 6][pr] = pk2(fmaf(a1.z, 1e38f, -1e38f));
        mpack[pj + 7][pr] = pk2(fmaf(a1.w, 1e38f, -1e38f));
    }

    float4 acc[8];
#pragma unroll
    for (int r = 0; r < 8; ++r)
        acc[r] = make_float4(-3.0e38f, -3.0e38f, -3.0e38f, -3.0e38f);

    for (int c = 0; c < 8; ++c) {
        if (c < 7) {      // stage next chunk into the other buffer
            unsigned dst = (unsigned)__cvta_generic_to_shared(
                               qbuf + ((c + 1) & 1) * 2048);
#pragma unroll
            for (int t = 0; t < 4; ++t) {
                const int idx = tid + t * 512;
                cpasync16(dst + idx * 16, Qb4 + (c + 1) * 2048 + idx);
            }
            CP_COMMIT();
            CP_WAIT(1);   // chunk c arrived (1 group still in flight)
        } else {
            CP_WAIT(0);
        }
        __syncthreads();

        const float4* qc = qbuf + (c & 1) * 2048;
        const int jb = w * 4;
#pragma unroll
        for (int u = 0; u < 4; ++u) {
            const int jl = jb + u;
            const int jg = c * 64 + jl;
            F4U2 q;
            q.f4 = qc[jl * 32 + lane];

#define MROW2(ra, rb, mm2) {                                      \
            F4U2 ta, tb;                                          \
            ta.u[0] = add2(q.u[0], (mm2).x);                      \
            ta.u[1] = add2(q.u[1], (mm2).x);                      \
            tb.u[0] = add2(q.u[0], (mm2).y);                      \
            tb.u[1] = add2(q.u[1], (mm2).y);                      \
            acc[ra] = f4max(acc[ra], ta.f4);                      \
            acc[rb] = f4max(acc[rb], tb.f4); }

            { const ulonglong2 m01 = *(const ulonglong2*)&mpack[jg][0];
              MROW2(0, 1, m01) }
            { const ulonglong2 m23 = *(const ulonglong2*)&mpack[jg][2];
              MROW2(2, 3, m23) }
            { const ulonglong2 m45 = *(const ulonglong2*)&mpack[jg][4];
              MROW2(4, 5, m45) }
            { const ulonglong2 m67 = *(const ulonglong2*)&mpack[jg][6];
              MROW2(6, 7, m67) }
#undef MROW2
        }
        __syncthreads();   // before next stage overwrites buffer (c+1)&1
    }

    // ---- log-tree reduction 16 -> 1 warps (reuse qbuf) ----
    float4 (*buf)[8][32] = (float4 (*)[8][32])qbuf;

#define WRITE_ACC(slot) {                                         \
    _Pragma("unroll")                                             \
    for (int r = 0; r < 8; ++r) buf[slot][r][lane] = acc[r]; }
#define MERGE_ACC(slot) {                                         \
    _Pragma("unroll")                                             \
    for (int r = 0; r < 8; ++r)                                   \
        acc[r] = f4max(acc[r], buf[slot][r][lane]); }

    if (w >= 8 && w < 12) WRITE_ACC(w - 8);
    __syncthreads();
    if (w < 4) MERGE_ACC(w);
    __syncthreads();
    if (w >= 12) WRITE_ACC(w - 12);
    __syncthreads();
    if (w >= 4 && w < 8) MERGE_ACC(w - 4);
    __syncthreads();
    if (w >= 4 && w < 8) WRITE_ACC(w - 4);
    __syncthreads();
    if (w < 4) MERGE_ACC(w);
    __syncthreads();
    if (w == 2 || w == 3) WRITE_ACC(w - 2);
    __syncthreads();
    if (w < 2) MERGE_ACC(w);
    __syncthreads();
    if (w == 1) WRITE_ACC(0);
    __syncthreads();

    if (w == 0) {
        MERGE_ACC(0);
        const float4* __restrict__ P4 = (const float4*)g_Pb;
        float4* __restrict__ O4 = (float4*)out;
#pragma unroll
        for (int r = 0; r < 8; ++r) {
            const float4 p = __ldg(&P4[(size_t)(i0 + r) * 32 + lane]);
            float4 o;
            o.x = fmaxf(0.f, p.x + acc[r].x);
            o.y = fmaxf(0.f, p.y + acc[r].y);
            o.z = fmaxf(0.f, p.z + acc[r].z);
            o.w = fmaxf(0.f, p.w + acc[r].w);
            O4[(size_t)(i0 + r) * 32 + lane] = o;
        }
    }
#undef WRITE_ACC
#undef MERGE_ACC
}

// ---------------------------------------------------------------------------
extern "C" void kernel_launch(void* const* d_in, const int* in_sizes, int n_in,
                              void* d_out, int out_size) {
    const float* x    = (const float*)d_in[0];   // (4,512,128)
    const float* adj  = (const float*)d_in[1];   // (4,512,512)
    const float* W    = (const float*)d_in[2];   // (256,128)
    const float* bias = (const float*)d_in[3];   // (128,)
    float*       out  = (float*)d_out;           // (4,512,128)

    const int DSM = 65536 + 32768;               // 96 KB dynamic smem
    cudaFuncSetAttribute(ec_maxred_kernel,
                         cudaFuncAttributeMaxDynamicSharedMemorySize, DSM);

    ec_gemm_kernel<<<M_TOTAL / 4, 128>>>(x, W, bias);
    ec_maxred_kernel<<<M_TOTAL / 8, 512, DSM>>>(adj, out);
}